// round 4
// baseline (speedup 1.0000x reference)
#include <cuda_runtime.h>
#include <math_constants.h>

// MSE+BPR pairwise loss, N=16384.
// total = sum over ordered pairs (i,j) with t[j] > t[i] of
//         0.5*softplus(in[i]-in[j]) + 0.5*(in[i]-t[i])^2
// out = total * 2/N^2
//
// Off-diagonal fast path per unordered pair {i,j}:
//   softplus(directed d) = max(s*d, 0) + ln2 * log2(1+exp(-|d|))
//   log2 terms batched: one MUFU.LG2 per 8 pairs via product of (1+e).
//   MSE: count of (t_j > t_i) per row (int) + masked sum of column mse.
//   Exact target ties (prob ~1e-7 of the sum) approximated as t_i > t_j.
// Diagonal tiles use the exact fully-predicated path (3% of work).

#define TILE 256

__device__ double g_accum;

__global__ void mb_zero_kernel() { g_accum = 0.0; }

__global__ void mb_finalize_kernel(float* out, int n) {
    double scale = 2.0 / ((double)n * (double)n);
    out[0] = (float)(g_accum * scale);
}

__global__ void __launch_bounds__(TILE, 8)
mb_pair_kernel(const float* __restrict__ inp,
               const float* __restrict__ tgt,
               int n) {
    const int bi = blockIdx.y;   // row tile
    const int bj = blockIdx.x;   // col tile
    if (bi > bj) return;         // upper-triangular tiles only (uniform exit)

    __shared__ float4 sc[TILE];      // {x_j, t_j, mse_j, 0}
    __shared__ double red[TILE];

    const int tid = threadIdx.x;
    const int ig = bi * TILE + tid;
    const int jg = bj * TILE + tid;

    // Pad with -INF: pad column in a full tile contributes exactly 0
    // (d0=+INF -> e=0, u=1, relu(-INF)=0, m1 false, mse=0).
    float xi = -CUDART_INF_F, ti = -CUDART_INF_F, mi = 0.0f;
    if (ig < n) {
        xi = inp[ig]; ti = tgt[ig];
        float dm = xi - ti; mi = dm * dm;
    }
    float xj = -CUDART_INF_F, tj = -CUDART_INF_F, mj = 0.0f;
    if (jg < n) {
        xj = inp[jg]; tj = tgt[jg];
        float dm = xj - tj; mj = dm * dm;
    }
    sc[tid] = make_float4(xj, tj, mj, 0.0f);
    __syncthreads();

    float acc_l2  = 0.0f;   // sum of log2(1 + exp(-|d|))
    float acc_lin = 0.0f;   // sum of relu(directed d)
    float acc_mj  = 0.0f;   // sum of column mse where t_i > t_j
    int   cnti    = 0;      // # pairs where t_j > t_i (row mse multiplier)

    if (bi != bj) {
        // Full 256x256 tile: every (i,j) is a distinct unordered pair.
        #pragma unroll 2
        for (int j0 = 0; j0 < TILE; j0 += 8) {
            float p0 = 1.0f, p1 = 1.0f;   // two chains for ILP
            #pragma unroll
            for (int k = 0; k < 8; ++k) {
                float4 c = sc[j0 + k];
                float d0 = xi - c.x;                 // in_i - in_j
                bool  m1 = c.y > ti;                 // t_j > t_i
                float e  = __expf(-fabsf(d0));       // FMUL(|.|,neg) + MUFU.EX2
                float u  = 1.0f + e;                 // in (1, 2]
                if (k & 1) p1 *= u; else p0 *= u;
                float sd = m1 ? d0 : -d0;            // FSEL
                acc_lin += fmaxf(sd, 0.0f);          // FMNMX + FADD
                if (m1) cnti++;                      // @p IADD (alu pipe)
                else    acc_mj += c.z;               // @!p FADD
            }
            acc_l2 += __log2f(p0 * p1);              // 1 LG2 per 8 pairs
        }
    } else {
        // Diagonal tile: strict upper triangle, exact tie handling.
        for (int j = tid + 1; j < TILE; ++j) {
            float4 c = sc[j];
            float d0 = xi - c.x;
            bool m1 = c.y > ti;
            bool m2 = ti  > c.y;
            float l2 = __log2f(1.0f + __expf(-fabsf(d0)));
            if (m1 | m2) {
                acc_l2  += l2;
                acc_lin += fmaxf(m1 ? d0 : -d0, 0.0f);
            }
            if (m1) cnti++;
            if (m2) acc_mj += c.z;
        }
    }

    // part = 0.5*(relu + ln2*log2sum) + 0.5*(cnt*mse_i + sum mse_j)
    double part = 0.5 * ((double)acc_lin + 0.69314718055994530942 * (double)acc_l2)
                + 0.5 * ((double)cnti * (double)mi + (double)acc_mj);

    red[tid] = part;
    __syncthreads();
    #pragma unroll
    for (int s = TILE / 2; s > 0; s >>= 1) {
        if (tid < s) red[tid] += red[tid + s];
        __syncthreads();
    }
    if (tid == 0) atomicAdd(&g_accum, red[0]);
}

extern "C" void kernel_launch(void* const* d_in, const int* in_sizes, int n_in,
                              void* d_out, int out_size) {
    const float* inp = (const float*)d_in[0];
    const float* tgt = (const float*)d_in[1];
    float* out = (float*)d_out;
    int n = in_sizes[0];

    int nb = (n + TILE - 1) / TILE;
    dim3 grid(nb, nb);

    mb_zero_kernel<<<1, 1>>>();
    mb_pair_kernel<<<grid, TILE>>>(inp, tgt, n);
    mb_finalize_kernel<<<1, 1>>>(out, n);
}

// round 6
// speedup vs baseline: 1.5048x; 1.5048x over previous
#include <cuda_runtime.h>
#include <math_constants.h>

// MSE+BPR pairwise loss, N=16384.
// total = sum over ordered pairs (i,j), t[j] > t[i], of
//         0.5*softplus(in[i]-in[j]) + 0.5*(in[i]-t[i])^2 ; out = total*2/N^2
//
// Fast path (full off-diagonal 256x256 tiles), per unordered pair, in
// log2-units (inputs pre-scaled by log2(e)):
//   softplus parts: relu = (|g| + s*g)/2 with s=+1 iff t_j > t_i;
//   Sum s*g = 2*D - T with T tile-constant. log2(1+e) batched 8-wide via
//   product p = fma(p, e, p), one lg2 per 8 pairs.
//   MSE: per-row count of (t_j > t_i) (int) + masked sum of column mse.
//   Exact target ties (measure ~0 of the sum) treated as t_i > t_j.
// Diagonal / ragged tiles use an exact fully-gated path.

#define TILE 256
#define LOG2E_F 1.4426950408889634074f
#define LN2_D   0.69314718055994530942

__device__ double g_accum;

__global__ void mb_zero_kernel() { g_accum = 0.0; }

__global__ void mb_finalize_kernel(float* out, int n) {
    out[0] = (float)(g_accum * (2.0 / ((double)n * (double)n)));
}

__device__ __forceinline__ float ex2f(float x) {
    float r; asm("ex2.approx.ftz.f32 %0, %1;" : "=f"(r) : "f"(x)); return r;
}
__device__ __forceinline__ float lg2f(float x) {
    float r; asm("lg2.approx.ftz.f32 %0, %1;" : "=f"(r) : "f"(x)); return r;
}

__global__ void __launch_bounds__(TILE)
mb_pair_kernel(const float* __restrict__ inp,
               const float* __restrict__ tgt,
               int n, int nb) {
    // Decode linear block index -> (bi, bj) with bi <= bj (upper triangle).
    // off(bi) = bi*nb - bi*(bi-1)/2
    const int b = blockIdx.x;
    int bi = (int)((2.0 * nb + 1.0 -
                    sqrt((2.0 * nb + 1.0) * (2.0 * nb + 1.0) - 8.0 * (double)b)) * 0.5);
    if (bi < 0) bi = 0;
    if (bi >= nb) bi = nb - 1;
    while (bi > 0 && ((long long)bi * nb - (long long)bi * (bi - 1) / 2) > b) bi--;
    while (((long long)(bi + 1) * nb - (long long)(bi + 1) * bi / 2) <= b) bi++;
    const int bj = bi + (int)(b - ((long long)bi * nb - (long long)bi * (bi - 1) / 2));

    __shared__ float4 sc[TILE];     // {x_j*log2e, t_j, mse_j, 0}
    __shared__ float  sg[TILE];
    __shared__ double red[TILE];

    const int tid = threadIdx.x;
    const int ig = bi * TILE + tid;
    const int jg = bj * TILE + tid;

    // NaN target padding: all compares false in the gated path.
    float xi2 = 0.0f, ti = CUDART_NAN_F, mi = 0.0f;
    if (ig < n) {
        float x = inp[ig]; ti = tgt[ig];
        xi2 = x * LOG2E_F;
        float dm = x - ti; mi = dm * dm;
    }
    float xj2 = 0.0f, tj = CUDART_NAN_F, mj = 0.0f;
    if (jg < n) {
        float x = inp[jg]; tj = tgt[jg];
        xj2 = x * LOG2E_F;
        float dm = x - tj; mj = dm * dm;
    }
    sc[tid] = make_float4(xj2, tj, mj, 0.0f);
    sg[tid] = xj2;
    __syncthreads();

    // Tile-wide sum of scaled x_j (for the T term in the fast path).
    #pragma unroll
    for (int s = TILE / 2; s > 0; s >>= 1) {
        if (tid < s) sg[tid] += sg[tid + s];
        __syncthreads();
    }
    const float sumG = sg[0];

    float L2 = 0.0f;    // sum log2(1 + exp2(-|g|))
    float LIN = 0.0f;   // sum relu(s*g) in log2 units
    float A = 0.0f;     // sum |g|
    float D = 0.0f;     // sum g over pairs with t_j > t_i
    float Mj = 0.0f;    // sum mse_j over pairs with t_i > t_j
    int   cnt = 0;      // # pairs with t_j > t_i

    const bool full = ((bi + 1) * TILE <= n) && ((bj + 1) * TILE <= n);
    if ((bi != bj) & full) {
        for (int j0 = 0; j0 < TILE; j0 += 8) {
            float p0 = 1.0f, p1 = 1.0f;    // two product chains for ILP
            #pragma unroll
            for (int k = 0; k < 8; ++k) {
                float4 c = sc[j0 + k];
                float g  = xi2 - c.x;            // FADD
                float hg = fmaxf(g, -g);         // FMNMX (|g|)
                float e  = ex2f(-hg);            // MUFU.EX2 (neg folds in)
                if (k & 1) p1 = fmaf(p1, e, p1); // FFMA: p *= (1+e)
                else       p0 = fmaf(p0, e, p0);
                A += hg;                         // FADD (unconditional)
                bool m1 = c.y > ti;              // FSETP
                if (m1) { D += g; cnt++; }       // @p FADD + @p IADD
                else    { Mj += c.z; }           // @!p FADD
            }
            L2 += lg2f(p0 * p1);                 // 1 LG2 per 8 pairs
        }
        // relu sum (log2 units) = 0.5*(A + 2D - T), T = 256*xi2 - sumG
        LIN = 0.5f * (A + 2.0f * D - (256.0f * xi2 - sumG));
    } else {
        // Exact gated path: diagonal (j > i) and ragged tiles.
        const int jstart = (bi == bj) ? tid + 1 : 0;
        for (int j = jstart; j < TILE; ++j) {
            float4 c = sc[j];
            float g = xi2 - c.x;
            bool m1 = c.y > ti;
            bool m2 = ti > c.y;
            float l2v = lg2f(1.0f + ex2f(-fmaxf(g, -g)));
            if (m1 | m2) {
                L2  += l2v;
                LIN += fmaxf(m1 ? g : -g, 0.0f);
            }
            if (m1) cnt++;
            if (m2) Mj += c.z;
        }
    }

    // part = 0.5*ln2*(LIN + L2)  +  0.5*(cnt*mse_i + sum mse_j)
    double part = 0.5 * (LN2_D * ((double)LIN + (double)L2))
                + 0.5 * ((double)cnt * (double)mi + (double)Mj);

    red[tid] = part;
    __syncthreads();
    #pragma unroll
    for (int s = TILE / 2; s > 0; s >>= 1) {
        if (tid < s) red[tid] += red[tid + s];
        __syncthreads();
    }
    if (tid == 0) atomicAdd(&g_accum, red[0]);
}

extern "C" void kernel_launch(void* const* d_in, const int* in_sizes, int n_in,
                              void* d_out, int out_size) {
    const float* inp = (const float*)d_in[0];
    const float* tgt = (const float*)d_in[1];
    float* out = (float*)d_out;
    int n = in_sizes[0];

    int nb = (n + TILE - 1) / TILE;
    int nblocks = nb * (nb + 1) / 2;

    mb_zero_kernel<<<1, 1>>>();
    mb_pair_kernel<<<nblocks, TILE>>>(inp, tgt, n, nb);
    mb_finalize_kernel<<<1, 1>>>(out, n);
}